// round 16
// baseline (speedup 1.0000x reference)
#include <cuda_runtime.h>

// Problem dims
#define BSZ   512
#define TT    50
#define DIN   1024
#define DH0   2048
#define DH1   1024
#define DOUTD 1024

// ---------------- scratch arena ----------------
constexpr size_t CUR0_N = (size_t)BSZ * TT * DH0;   // 52,428,800 f32
constexpr size_t C0_N   = (size_t)BSZ * DH0;
constexpr size_t VEC_N  = (size_t)BSZ * DOUTD;

constexpr size_t aup(size_t x) { return (x + 1023) & ~(size_t)1023; }

constexpr size_t OFF_CUR0 = 0;
constexpr size_t OFF_C0   = aup(OFF_CUR0 + CUR0_N * 4);
constexpr size_t OFF_CUR1 = aup(OFF_C0   + C0_N * 4);
constexpr size_t OFF_C1   = aup(OFF_CUR1 + VEC_N * 4);
constexpr size_t OFF_CUR2 = aup(OFF_C1   + VEC_N * 4);
constexpr size_t OFF_C2   = aup(OFF_CUR2 + VEC_N * 4);
constexpr size_t OFF_CUR3 = aup(OFF_C2   + VEC_N * 4);
constexpr size_t OFF_C3   = aup(OFF_CUR3 + VEC_N * 4);
constexpr size_t OFF_CUR4 = aup(OFF_C3   + VEC_N * 4);
constexpr size_t SCRATCH_BYTES = aup(OFF_CUR4 + VEC_N * 4);

__device__ __align__(1024) unsigned char g_scratch[SCRATCH_BYTES];

// ---------------- output layout (out, s0, s1, s2) ----------------
constexpr size_t OUT_OFF = 0;
constexpr size_t S0_OFF  = (size_t)BSZ * DOUTD;
constexpr size_t S1_OFF  = S0_OFF + (size_t)BSZ * TT * DH0;
constexpr size_t S2_OFF  = S1_OFF + (size_t)BSZ * TT * DH1;

// ---------------- panel-ordered fp32 GEMM ----------------
// Per output element:
//   P_p = ascending fma chain over k within panel p (panels of KC; last
//         panel = K % KC), accumulator starts at 0
//   C   = ((P_0 + P_1) + P_2) + ...  (one fadd rounding per panel fold;
//   association proven irrelevant: R12==R15 bit-identical)
// KC == K -> pure chain. KC == K/s -> split-K=s.
// M % 64 == 0, N % 64 == 0, K % 8 == 0, KC % 8 == 0.
__global__ void gemm_panel_kernel(const float* __restrict__ A,
                                  const float* __restrict__ B,
                                  float* __restrict__ C,
                                  int M, int N, int K, int KC) {
    constexpr int BM = 64, BN = 64, BK = 8;
    __shared__ float As[BK][BM + 4];
    __shared__ float Bs[BK][BN + 4];

    const int tx = threadIdx.x & 15;        // 0..15 (n dir)
    const int ty = threadIdx.x >> 4;        // 0..15 (m dir)
    const int tile_m = blockIdx.y * BM;
    const int tile_n = blockIdx.x * BN;

    float acc[4][4] = {};     // current panel chain
    float carry[4][4] = {};   // folded panel sums

    int next_b = KC;

    for (int k0 = 0; k0 < K; k0 += BK) {
        // load A tile (64 m x 8 k) transposed into As[k][m]; threads 0..127
        if (threadIdx.x < 128) {
            int t = threadIdx.x;
            int m = t >> 1;            // 0..63
            int kq = (t & 1) * 4;      // 0 or 4
            float4 v = *reinterpret_cast<const float4*>(
                A + (size_t)(tile_m + m) * K + k0 + kq);
            As[kq + 0][m] = v.x;
            As[kq + 1][m] = v.y;
            As[kq + 2][m] = v.z;
            As[kq + 3][m] = v.w;
        } else {
            // load B tile (8 k x 64 n); threads 128..255
            int u = threadIdx.x - 128;
            int kk = u >> 4;           // 0..7
            int nq = (u & 15) * 4;     // 0..60
            float4 v = *reinterpret_cast<const float4*>(
                B + (size_t)(k0 + kk) * N + tile_n + nq);
            *reinterpret_cast<float4*>(&Bs[kk][nq]) = v;
        }
        __syncthreads();

#pragma unroll
        for (int kk = 0; kk < BK; kk++) {   // ascending k — DO NOT REORDER
            float4 a = *reinterpret_cast<const float4*>(&As[kk][ty * 4]);
            float4 b = *reinterpret_cast<const float4*>(&Bs[kk][tx * 4]);
            float av[4] = {a.x, a.y, a.z, a.w};
            float bv[4] = {b.x, b.y, b.z, b.w};
#pragma unroll
            for (int i = 0; i < 4; i++)
#pragma unroll
                for (int j = 0; j < 4; j++)
                    acc[i][j] = fmaf(av[i], bv[j], acc[i][j]);
        }
        __syncthreads();

        int kend = k0 + BK;
        if (kend == next_b || kend == K) {   // panel boundary: fold into carry
#pragma unroll
            for (int i = 0; i < 4; i++)
#pragma unroll
                for (int j = 0; j < 4; j++) {
                    carry[i][j] = __fadd_rn(carry[i][j], acc[i][j]);
                    acc[i][j] = 0.0f;
                }
            next_b += KC;
        }
    }

#pragma unroll
    for (int i = 0; i < 4; i++) {
        float4 o = make_float4(carry[i][0], carry[i][1], carry[i][2],
                               carry[i][3]);
        *reinterpret_cast<float4*>(
            C + (size_t)(tile_m + ty * 4 + i) * N + tile_n + tx * 4) = o;
    }
}

// ---------------- LIF kernels ----------------
// v = rn(0.25*v + rn(0.75*c))  (0.25*v exact: power of two => fadd == fma)
__device__ __forceinline__ float lif_step(float& v, float c) {
    v = fmaf(0.25f, v, __fmul_rn(0.75f, c));
    float s = (v > 1.0f) ? 1.0f : 0.0f;
    v = __fsub_rn(v, s);
    return s;
}

// layer 0: time-varying currents cur[b][t][h]
__global__ void lif_seq_kernel(const float* __restrict__ cur,
                               const float* __restrict__ bias,
                               float* __restrict__ s_out,
                               float* __restrict__ cnt_out,
                               int B, int H) {
    int idx = blockIdx.x * blockDim.x + threadIdx.x;
    if (idx >= B * H) return;
    int b = idx / H, h = idx % H;
    float bb = bias[h];
    const float* cp = cur + (size_t)b * TT * H + h;
    float* sp = s_out + (size_t)b * TT * H + h;
    float v = 0.0f, cnt = 0.0f;
#pragma unroll 5
    for (int t = 0; t < TT; t++) {
        float c = __fadd_rn(cp[(size_t)t * H], bb);
        float s = lif_step(v, c);
        sp[(size_t)t * H] = s;
        cnt += s;   // integer <= 50, exact
    }
    cnt_out[idx] = cnt;
}

// layers 1..3: constant current per (b,h)
template <bool WRITE_SPIKES>
__global__ void lif_const_kernel(const float* __restrict__ cur,
                                 const float* __restrict__ bias,
                                 float* __restrict__ s_out,
                                 float* __restrict__ cnt_out,
                                 int B, int H) {
    int idx = blockIdx.x * blockDim.x + threadIdx.x;
    if (idx >= B * H) return;
    int b = idx / H, h = idx % H;
    float c = __fadd_rn(cur[idx], bias[h]);
    float* sp = WRITE_SPIKES ? (s_out + (size_t)b * TT * H + h) : nullptr;
    float v = 0.0f, cnt = 0.0f;
#pragma unroll
    for (int t = 0; t < TT; t++) {
        float s = lif_step(v, c);
        if (WRITE_SPIKES) sp[(size_t)t * H] = s;
        cnt += s;
    }
    cnt_out[idx] = cnt;
}

__global__ void final_out_kernel(const float* __restrict__ cur,
                                 const float* __restrict__ bout,
                                 float* __restrict__ out) {
    int i = blockIdx.x * blockDim.x + threadIdx.x;
    if (i >= BSZ * DOUTD) return;
    out[i] = __fadd_rn(cur[i], bout[i & (DOUTD - 1)]);
}

// ---------------- launch ----------------
extern "C" void kernel_launch(void* const* d_in, const int* in_sizes, int n_in,
                              void* d_out, int out_size) {
    const float* x    = (const float*)d_in[0];
    const float* W0   = (const float*)d_in[1];
    const float* b0   = (const float*)d_in[2];
    const float* W1   = (const float*)d_in[3];
    const float* b1   = (const float*)d_in[4];
    const float* W2   = (const float*)d_in[5];
    const float* b2   = (const float*)d_in[6];
    const float* Wout = (const float*)d_in[7];
    const float* bout = (const float*)d_in[8];
    float* out = (float*)d_out;

    unsigned char* base = nullptr;
    cudaGetSymbolAddress((void**)&base, g_scratch);

    float* cur0 = (float*)(base + OFF_CUR0);
    float* c0   = (float*)(base + OFF_C0);
    float* cur1 = (float*)(base + OFF_CUR1);
    float* c1   = (float*)(base + OFF_C1);
    float* cur2 = (float*)(base + OFF_CUR2);
    float* c2   = (float*)(base + OFF_C2);
    float* cur3 = (float*)(base + OFF_CUR3);
    float* c3   = (float*)(base + OFF_C3);
    float* cur4 = (float*)(base + OFF_CUR4);

    // 1) cur0 = x @ W0 (25600x2048x1024): big-M -> PURE CHAIN (locked)
    gemm_panel_kernel<<<dim3(DH0 / 64, (BSZ * TT) / 64), 256>>>(
        x, W0, cur0, BSZ * TT, DH0, DIN, DIN);
    // 2) LIF layer 0 -> s0 + counts
    lif_seq_kernel<<<(BSZ * DH0 + 255) / 256, 256>>>(cur0, b0, out + S0_OFF,
                                                     c0, BSZ, DH0);
    // 3) cur1 = c0 @ W1 (512x1024x2048): split-K=4 -> KC=512 (locked by
    //    R12: only value below 2e-3)
    gemm_panel_kernel<<<dim3(DH1 / 64, BSZ / 64), 256>>>(c0, W1, cur1,
                                                         BSZ, DH1, DH0, 512);
    lif_const_kernel<true><<<(BSZ * DH1 + 255) / 256, 256>>>(
        cur1, b1, out + S1_OFF, c1, BSZ, DH1);
    // 4) cur2 = c1 @ W2 (512x1024x1024): split-K=2 -> KC=512
    //    (column-optimum from L1@1024 row: 512 < chain < 256)
    gemm_panel_kernel<<<dim3(DOUTD / 64, BSZ / 64), 256>>>(c1, W2, cur2,
                                                           BSZ, DOUTD, DH1,
                                                           512);
    lif_const_kernel<true><<<(BSZ * DOUTD + 255) / 256, 256>>>(
        cur2, b2, out + S2_OFF, c2, BSZ, DOUTD);
    // 5) cur3 = c2 @ W2 again: split-K=2 -> KC=512
    gemm_panel_kernel<<<dim3(DOUTD / 64, BSZ / 64), 256>>>(c2, W2, cur3,
                                                           BSZ, DOUTD, DH1,
                                                           512);
    lif_const_kernel<false><<<(BSZ * DOUTD + 255) / 256, 256>>>(
        cur3, b2, nullptr, c3, BSZ, DOUTD);
    // 6) out = c3 @ Wout + bout: split-K=2 -> KC=512
    gemm_panel_kernel<<<dim3(DOUTD / 64, BSZ / 64), 256>>>(c3, Wout, cur4,
                                                           BSZ, DOUTD, DOUTD,
                                                           512);
    final_out_kernel<<<(BSZ * DOUTD + 255) / 256, 256>>>(cur4, bout,
                                                         out + OUT_OFF);
}